// round 12
// baseline (speedup 1.0000x reference)
#include <cuda_runtime.h>

#define NN 100000
#define EE 1600000
#define NB 98   // ceil(NN/1024)

// ---------------- scratch (static __device__ globals) ------------------------
__device__ float  g_dinv[NN];
__device__ float  g_nself[NN];
__device__ int    g_cnt[NN];
__device__ int    g_incl[NN];
__device__ int    g_bsum[NB];
__device__ int    g_boff[NB];
__device__ int    g_rowptr[NN + 1];
__device__ int    g_cursor[NN];
__device__ float2 g_csr[EE];          // (src_as_float, norm_w) packed
__device__ float  g_a1[NN];           // A_hat @ ones
__device__ float  g_a2[NN];           // A_hat^2 @ ones
__device__ float  g_Wc[64 * 32];      // W1 @ W2 @ W3
__device__ float  g_bt1[32];          // b1 @ W2 @ W3
__device__ float  g_bt2[32];          // b2 @ W3
__device__ float  g_bufA[(size_t)NN * 32];
__device__ float  g_bufB[(size_t)NN * 32];

enum Buf { BA, BB };
template <Buf B> __device__ __forceinline__ float* bufp() {
    return (B == BA) ? g_bufA : g_bufB;
}

// ---------------- setup ------------------------------------------------------
__global__ void k_init() {
    int i = blockIdx.x * blockDim.x + threadIdx.x;
    if (i < NN) { g_dinv[i] = 1.0f; g_cnt[i] = 0; }
}

__global__ void k_deg(const int* __restrict__ ei, const float* __restrict__ w) {
    int e = blockIdx.x * blockDim.x + threadIdx.x;
    if (e < EE) {
        int c = ei[EE + e];
        atomicAdd(g_dinv + c, w[e]);
        atomicAdd(g_cnt + c, 1);
    }
}

__global__ void k_dinv() {
    int i = blockIdx.x * blockDim.x + threadIdx.x;
    if (i < NN) {
        float d = rsqrtf(g_dinv[i]);
        g_dinv[i] = d;
        g_nself[i] = d * d;
    }
}

__global__ void __launch_bounds__(1024) k_scan1() {
    __shared__ int s[1024];
    int i = blockIdx.x * 1024 + threadIdx.x;
    int v = (i < NN) ? g_cnt[i] : 0;
    s[threadIdx.x] = v;
    __syncthreads();
    for (int d = 1; d < 1024; d <<= 1) {
        int t = (threadIdx.x >= d) ? s[threadIdx.x - d] : 0;
        __syncthreads();
        s[threadIdx.x] += t;
        __syncthreads();
    }
    if (i < NN) g_incl[i] = s[threadIdx.x];
    if (threadIdx.x == 1023) g_bsum[blockIdx.x] = s[1023];
}

__global__ void k_scan2() {
    __shared__ int s[128];
    int v = (threadIdx.x < NB) ? g_bsum[threadIdx.x] : 0;
    s[threadIdx.x] = v;
    __syncthreads();
    for (int d = 1; d < 128; d <<= 1) {
        int t = (threadIdx.x >= d) ? s[threadIdx.x - d] : 0;
        __syncthreads();
        s[threadIdx.x] += t;
        __syncthreads();
    }
    if (threadIdx.x < NB) g_boff[threadIdx.x] = s[threadIdx.x] - v;  // exclusive
}

__global__ void k_finalize() {
    int i = blockIdx.x * blockDim.x + threadIdx.x;
    if (i < NN) {
        int ex = g_incl[i] - g_cnt[i] + g_boff[i >> 10];
        g_rowptr[i] = ex;
        g_cursor[i] = ex;
    }
    if (i == 0) g_rowptr[NN] = EE;
}

__global__ void k_scatter(const int* __restrict__ ei, const float* __restrict__ w) {
    int e = blockIdx.x * blockDim.x + threadIdx.x;
    if (e < EE) {
        int r = ei[e];
        int c = ei[EE + e];
        float ne = g_dinv[r] * w[e] * g_dinv[c];
        int pos = atomicAdd(g_cursor + c, 1);
        float2 p = {__int_as_float(r), ne};
        g_csr[pos] = p;
    }
}

// ---------------- collapsed weights: Wc = W1@W2@W3, bt1 = b1@W2@W3, bt2 = b2@W3
__global__ void __launch_bounds__(256) k_wc(
        const float* __restrict__ W1, const float* __restrict__ W2,
        const float* __restrict__ W3, const float* __restrict__ b1,
        const float* __restrict__ b2) {
    __shared__ float sW12[64 * 64];
    __shared__ float sbw[64];
    int t = threadIdx.x;   // 256
    for (int i = t; i < 64 * 64; i += 256) {
        int r = i >> 6, c = i & 63;
        float s = 0.f;
        for (int k = 0; k < 128; k++) s += W1[r * 128 + k] * W2[k * 64 + c];
        sW12[i] = s;
    }
    if (t < 64) {
        float s = 0.f;
        for (int k = 0; k < 128; k++) s += b1[k] * W2[k * 64 + t];
        sbw[t] = s;
    }
    __syncthreads();
    for (int i = t; i < 64 * 32; i += 256) {
        int r = i >> 5, c = i & 31;
        float s = 0.f;
        for (int k = 0; k < 64; k++) s += sW12[r * 64 + k] * W3[k * 32 + c];
        g_Wc[i] = s;
    }
    if (t < 32) {
        float s1 = 0.f, s2 = 0.f;
        for (int k = 0; k < 64; k++) {
            s1 += sbw[k] * W3[k * 32 + t];
            s2 += b2[k] * W3[k * 32 + t];
        }
        g_bt1[t] = s1;
        g_bt2[t] = s2;
    }
}

// ---------------- a1 = A_hat @ 1 (thread/node, streaming) ---------------------
__global__ void k_a1() {
    int i = blockIdx.x * blockDim.x + threadIdx.x;
    if (i < NN) {
        int beg = g_rowptr[i], end = g_rowptr[i + 1];
        float s = g_nself[i];
        for (int j = beg; j < end; j++) s += g_csr[j].y;
        g_a1[i] = s;
    }
}

// ---------------- a2 = A_hat @ a1 (warp/node, lane-parallel + reduce) ---------
__global__ void __launch_bounds__(256) k_a2() {
    int node = blockIdx.x * 8 + (threadIdx.x >> 5);
    int lane = threadIdx.x & 31;
    if (node >= NN) return;
    int beg = g_rowptr[node], end = g_rowptr[node + 1];
    float s = 0.f;
    for (int j = beg + lane; j < end; j += 32) {
        float2 e = g_csr[j];
        s += e.y * __ldg(g_a1 + __float_as_int(e.x));
    }
#pragma unroll
    for (int o = 16; o > 0; o >>= 1) s += __shfl_xor_sync(0xffffffffu, s, o);
    if (lane == 0) g_a2[node] = s + g_nself[node] * g_a1[node];
}

// ---------------- width-32 aggregation: warp/node, 4 edges per iteration ------
// lane = grp*8 + ch; grp = edge slot (0..3), ch = float4 chunk (0..7).
// Each iteration the warp gathers 4 full 128B rows. Partials combined by
// shfl_xor(8,16); group 0 holds self term + epilogue + row write.
template <bool FINAL, Buf HB, Buf OB>
__global__ void __launch_bounds__(256) k_agg32(float* __restrict__ ox,
                                               const float* __restrict__ b3) {
    int node = blockIdx.x * 8 + (threadIdx.x >> 5);
    if (node >= NN) return;
    int lane = threadIdx.x & 31;
    int grp = lane >> 3;          // edge slot within iteration
    int ch = lane & 7;            // float4 chunk of the row
    const float* h = bufp<HB>();
    float* out = FINAL ? ox : bufp<OB>();

    int beg = g_rowptr[node];
    int end = g_rowptr[node + 1];

    float ax = 0.f, ay = 0.f, az = 0.f, aw = 0.f;
    if (grp == 0) {
        float s = g_nself[node];
        float4 v = __ldg((const float4*)(h + (size_t)node * 32 + ch * 4));
        ax = v.x * s; ay = v.y * s; az = v.z * s; aw = v.w * s;
    }

    int j = beg + grp;
    // unroll 2: up to 8 edges in flight per warp
    for (; j + 4 < end; j += 8) {
        float2 e0 = g_csr[j];
        float2 e1 = g_csr[j + 4];
        float4 u0 = __ldg((const float4*)(h + (size_t)__float_as_int(e0.x) * 32 + ch * 4));
        float4 u1 = __ldg((const float4*)(h + (size_t)__float_as_int(e1.x) * 32 + ch * 4));
        ax += u0.x * e0.y; ay += u0.y * e0.y; az += u0.z * e0.y; aw += u0.w * e0.y;
        ax += u1.x * e1.y; ay += u1.y * e1.y; az += u1.z * e1.y; aw += u1.w * e1.y;
    }
    if (j < end) {
        float2 e = g_csr[j];
        float4 u = __ldg((const float4*)(h + (size_t)__float_as_int(e.x) * 32 + ch * 4));
        ax += u.x * e.y; ay += u.y * e.y; az += u.z * e.y; aw += u.w * e.y;
    }

    // combine the 4 edge-slot partials (lanes differing in bits 3,4)
#pragma unroll
    for (int o = 8; o <= 16; o <<= 1) {
        ax += __shfl_xor_sync(0xffffffffu, ax, o);
        ay += __shfl_xor_sync(0xffffffffu, ay, o);
        az += __shfl_xor_sync(0xffffffffu, az, o);
        aw += __shfl_xor_sync(0xffffffffu, aw, o);
    }

    if (grp == 0) {
        if (FINAL) {
            float a1v = g_a1[node];
            float a2v = g_a2[node];
            float4 t1 = *(const float4*)(g_bt1 + ch * 4);
            float4 t2 = *(const float4*)(g_bt2 + ch * 4);
            float4 b = *(const float4*)(b3 + ch * 4);
            ax += a2v * t1.x + a1v * t2.x + b.x;
            ay += a2v * t1.y + a1v * t2.y + b.y;
            az += a2v * t1.z + a1v * t2.z + b.z;
            aw += a2v * t1.w + a1v * t2.w + b.w;
            ax = 1.f / (1.f + __expf(-ax));
            ay = 1.f / (1.f + __expf(-ay));
            az = 1.f / (1.f + __expf(-az));
            aw = 1.f / (1.f + __expf(-aw));
        }
        float4 o = {ax, ay, az, aw};
        *(float4*)(out + (size_t)node * 32 + ch * 4) = o;
    }
}

// ---------------- tensor-core GEMM (3xTF32, mma.sync m16n8k8) ----------------
__device__ __forceinline__ void split_tf32(float v, unsigned& hi, unsigned& lo) {
    unsigned h;
    asm("cvt.rna.tf32.f32 %0, %1;" : "=r"(h) : "f"(v));
    float hf = __uint_as_float(h);
    float l = v - hf;
    unsigned lb;
    asm("cvt.rna.tf32.f32 %0, %1;" : "=r"(lb) : "f"(l));
    hi = h; lo = lb;
}

__device__ __forceinline__ void mma_tf32(float* c, const unsigned* a,
                                         unsigned b0, unsigned b1) {
    asm volatile(
        "mma.sync.aligned.m16n8k8.row.col.f32.tf32.tf32.f32 "
        "{%0,%1,%2,%3}, {%4,%5,%6,%7}, {%8,%9}, {%0,%1,%2,%3};\n"
        : "+f"(c[0]), "+f"(c[1]), "+f"(c[2]), "+f"(c[3])
        : "r"(a[0]), "r"(a[1]), "r"(a[2]), "r"(a[3]), "r"(b0), "r"(b1));
}

// C[N,32] = A[N,64] @ Wc[64,32]. 256 thr = 8 warps x m16 = 128 rows/block.
__global__ void __launch_bounds__(256) k_gemm_xc(const float* __restrict__ A) {
    constexpr int IN = 64, OUT = 32;
    constexpr int KT = IN / 8, NT = OUT / 8, S = OUT + 8;
    float* C = g_bufA;

    __shared__ float sHi[IN * S];
    __shared__ float sLo[IN * S];

    int t = threadIdx.x;
    for (int i = t; i < IN * OUT; i += 256) {
        int k = i / OUT, n = i % OUT;
        unsigned hi, lo;
        split_tf32(g_Wc[i], hi, lo);
        sHi[k * S + n] = __uint_as_float(hi);
        sLo[k * S + n] = __uint_as_float(lo);
    }
    __syncthreads();

    int warp = t >> 5, lane = t & 31;
    int g = lane >> 2, tg = lane & 3;
    int row0 = blockIdx.x * 128 + warp * 16;

    float acc[NT][4];
#pragma unroll
    for (int n = 0; n < NT; n++)
#pragma unroll
        for (int j = 0; j < 4; j++) acc[n][j] = 0.f;

    int r0 = row0 + g;       if (r0 >= NN) r0 = NN - 1;
    int r1 = row0 + g + 8;   if (r1 >= NN) r1 = NN - 1;
    const float* Ar0 = A + (size_t)r0 * IN;
    const float* Ar1 = A + (size_t)r1 * IN;

#pragma unroll
    for (int k = 0; k < KT; k++) {
        float a0f = __ldg(Ar0 + k * 8 + tg);
        float a1f = __ldg(Ar1 + k * 8 + tg);
        float a2f = __ldg(Ar0 + k * 8 + tg + 4);
        float a3f = __ldg(Ar1 + k * 8 + tg + 4);
        unsigned ah[4], al[4];
        split_tf32(a0f, ah[0], al[0]);
        split_tf32(a1f, ah[1], al[1]);
        split_tf32(a2f, ah[2], al[2]);
        split_tf32(a3f, ah[3], al[3]);

        int kb0 = (k * 8 + tg) * S;
        int kb1 = (k * 8 + tg + 4) * S;
#pragma unroll
        for (int n = 0; n < NT; n++) {
            int nb = n * 8 + g;
            unsigned bh0 = __float_as_uint(sHi[kb0 + nb]);
            unsigned bh1 = __float_as_uint(sHi[kb1 + nb]);
            unsigned bl0 = __float_as_uint(sLo[kb0 + nb]);
            unsigned bl1 = __float_as_uint(sLo[kb1 + nb]);
            mma_tf32(acc[n], ah, bh0, bh1);
            mma_tf32(acc[n], ah, bl0, bl1);
            mma_tf32(acc[n], al, bh0, bh1);
        }
    }

    int sr0 = row0 + g;
    int sr1 = row0 + g + 8;
#pragma unroll
    for (int n = 0; n < NT; n++) {
        int c0 = n * 8 + tg * 2;
        if (sr0 < NN) {
            float2 o = {acc[n][0], acc[n][1]};
            *(float2*)(C + (size_t)sr0 * OUT + c0) = o;
        }
        if (sr1 < NN) {
            float2 o = {acc[n][2], acc[n][3]};
            *(float2*)(C + (size_t)sr1 * OUT + c0) = o;
        }
    }
}

// ---------------- launch ------------------------------------------------------
extern "C" void kernel_launch(void* const* d_in, const int* in_sizes, int n_in,
                              void* d_out, int out_size) {
    const float* x  = (const float*)d_in[0];
    const int*   ei = (const int*)d_in[1];     // int32 (JAX downcasts int64)
    const float* w  = (const float*)d_in[2];
    const float* W1 = (const float*)d_in[3];
    const float* b1 = (const float*)d_in[4];
    const float* W2 = (const float*)d_in[5];
    const float* b2 = (const float*)d_in[6];
    const float* W3 = (const float*)d_in[7];
    const float* b3 = (const float*)d_in[8];
    float* out = (float*)d_out;

    const int T = 256;
    // --- normalization + CSR build ---
    k_init<<<(NN + T - 1) / T, T>>>();
    k_deg<<<(EE + T - 1) / T, T>>>(ei, w);
    k_dinv<<<(NN + T - 1) / T, T>>>();
    k_scan1<<<NB, 1024>>>();
    k_scan2<<<1, 128>>>();
    k_finalize<<<(NN + T - 1) / T, T>>>();
    k_scatter<<<(EE + T - 1) / T, T>>>(ei, w);

    // --- collapsed weights + degree vectors ---
    k_wc<<<1, 256>>>(W1, W2, W3, b1, b2);
    k_a1<<<(NN + T - 1) / T, T>>>();
    k_a2<<<(NN + 7) / 8, T>>>();

    // --- xc = x @ Wc  -> bufA ---
    k_gemm_xc<<<(NN + 127) / 128, T>>>(x);

    // --- three width-32 aggregations (warp/node, 4 edges/iter) ---
    const int GA = (NN + 7) / 8;
    k_agg32<false, BA, BB><<<GA, T>>>(nullptr, nullptr);   // t1 -> bufB
    k_agg32<false, BB, BA><<<GA, T>>>(nullptr, nullptr);   // t2 -> bufA
    k_agg32<true,  BA, BA><<<GA, T>>>(out, b3);            // t3 (+bias,sigmoid) -> out
}

// round 13
// speedup vs baseline: 1.0860x; 1.0860x over previous
#include <cuda_runtime.h>

#define NN 100000
#define EE 1600000
#define NB 98   // ceil(NN/1024)

// ---------------- scratch (static __device__ globals) ------------------------
__device__ float  g_dinv[NN];
__device__ float  g_nself[NN];
__device__ int    g_cnt[NN];
__device__ int    g_incl[NN];
__device__ int    g_bsum[NB];
__device__ int    g_boff[NB];
__device__ int    g_rowptr[NN + 1];
__device__ int    g_cursor[NN];
__device__ float2 g_csr[EE];          // (src_as_float, norm_w) packed
__device__ float  g_a1[NN];           // A_hat @ ones
__device__ float  g_a2[NN];           // A_hat^2 @ ones
__device__ float  g_Wc[64 * 32];      // W1 @ W2 @ W3
__device__ float  g_bt1[32];          // b1 @ W2 @ W3
__device__ float  g_bt2[32];          // b2 @ W3
__device__ float  g_bufA[(size_t)NN * 32];
__device__ float  g_bufB[(size_t)NN * 32];

enum Buf { BA, BB };
template <Buf B> __device__ __forceinline__ float* bufp() {
    return (B == BA) ? g_bufA : g_bufB;
}

// ---------------- setup ------------------------------------------------------
__global__ void k_init() {
    int i = blockIdx.x * blockDim.x + threadIdx.x;
    if (i < NN) { g_dinv[i] = 1.0f; g_cnt[i] = 0; }
}

__global__ void k_deg(const int* __restrict__ ei, const float* __restrict__ w) {
    int e = blockIdx.x * blockDim.x + threadIdx.x;
    if (e < EE) {
        int c = ei[EE + e];
        atomicAdd(g_dinv + c, w[e]);
        atomicAdd(g_cnt + c, 1);
    }
}

__global__ void k_dinv() {
    int i = blockIdx.x * blockDim.x + threadIdx.x;
    if (i < NN) {
        float d = rsqrtf(g_dinv[i]);
        float ns = d * d;
        g_dinv[i] = d;
        g_nself[i] = ns;
        g_a1[i] = ns;          // seed a1 with self term; scatter adds edge terms
    }
}

__global__ void __launch_bounds__(1024) k_scan1() {
    __shared__ int s[1024];
    int i = blockIdx.x * 1024 + threadIdx.x;
    int v = (i < NN) ? g_cnt[i] : 0;
    s[threadIdx.x] = v;
    __syncthreads();
    for (int d = 1; d < 1024; d <<= 1) {
        int t = (threadIdx.x >= d) ? s[threadIdx.x - d] : 0;
        __syncthreads();
        s[threadIdx.x] += t;
        __syncthreads();
    }
    if (i < NN) g_incl[i] = s[threadIdx.x];
    if (threadIdx.x == 1023) g_bsum[blockIdx.x] = s[1023];
}

__global__ void k_scan2() {
    __shared__ int s[128];
    int v = (threadIdx.x < NB) ? g_bsum[threadIdx.x] : 0;
    s[threadIdx.x] = v;
    __syncthreads();
    for (int d = 1; d < 128; d <<= 1) {
        int t = (threadIdx.x >= d) ? s[threadIdx.x - d] : 0;
        __syncthreads();
        s[threadIdx.x] += t;
        __syncthreads();
    }
    if (threadIdx.x < NB) g_boff[threadIdx.x] = s[threadIdx.x] - v;  // exclusive
}

__global__ void k_finalize() {
    int i = blockIdx.x * blockDim.x + threadIdx.x;
    if (i < NN) {
        int ex = g_incl[i] - g_cnt[i] + g_boff[i >> 10];
        g_rowptr[i] = ex;
        g_cursor[i] = ex;
    }
    if (i == 0) g_rowptr[NN] = EE;
}

// scatter edges into CSR; also accumulate a1 (normalized in-weight sums)
__global__ void k_scatter(const int* __restrict__ ei, const float* __restrict__ w) {
    int e = blockIdx.x * blockDim.x + threadIdx.x;
    if (e < EE) {
        int r = ei[e];
        int c = ei[EE + e];
        float ne = g_dinv[r] * w[e] * g_dinv[c];
        int pos = atomicAdd(g_cursor + c, 1);
        float2 p = {__int_as_float(r), ne};
        g_csr[pos] = p;
        atomicAdd(g_a1 + c, ne);
    }
}

// ---------------- collapsed weights: Wc = W1@W2@W3, bt1 = b1@W2@W3, bt2 = b2@W3
__global__ void __launch_bounds__(256) k_wc(
        const float* __restrict__ W1, const float* __restrict__ W2,
        const float* __restrict__ W3, const float* __restrict__ b1,
        const float* __restrict__ b2) {
    __shared__ float sW12[64 * 64];
    __shared__ float sbw[64];
    int t = threadIdx.x;   // 256
    for (int i = t; i < 64 * 64; i += 256) {
        int r = i >> 6, c = i & 63;
        float s = 0.f;
        for (int k = 0; k < 128; k++) s += W1[r * 128 + k] * W2[k * 64 + c];
        sW12[i] = s;
    }
    if (t < 64) {
        float s = 0.f;
        for (int k = 0; k < 128; k++) s += b1[k] * W2[k * 64 + t];
        sbw[t] = s;
    }
    __syncthreads();
    for (int i = t; i < 64 * 32; i += 256) {
        int r = i >> 5, c = i & 31;
        float s = 0.f;
        for (int k = 0; k < 64; k++) s += sW12[r * 64 + k] * W3[k * 32 + c];
        g_Wc[i] = s;
    }
    if (t < 32) {
        float s1 = 0.f, s2 = 0.f;
        for (int k = 0; k < 64; k++) {
            s1 += sbw[k] * W3[k * 32 + t];
            s2 += b2[k] * W3[k * 32 + t];
        }
        g_bt1[t] = s1;
        g_bt2[t] = s2;
    }
}

// ---------------- a2 = A_hat @ a1 (warp/node, lane-parallel + reduce) ---------
__global__ void __launch_bounds__(256) k_a2() {
    int node = blockIdx.x * 8 + (threadIdx.x >> 5);
    int lane = threadIdx.x & 31;
    if (node >= NN) return;
    int beg = g_rowptr[node], end = g_rowptr[node + 1];
    float s = 0.f;
    for (int j = beg + lane; j < end; j += 32) {
        float2 e = g_csr[j];
        s += e.y * __ldg(g_a1 + __float_as_int(e.x));
    }
#pragma unroll
    for (int o = 16; o > 0; o >>= 1) s += __shfl_xor_sync(0xffffffffu, s, o);
    if (lane == 0) g_a2[node] = s + g_nself[node] * g_a1[node];
}

// ---------------- width-32 CSR aggregation: 8 thr/node, pipelined csr loads ---
template <bool FINAL, Buf HB, Buf OB>
__global__ void __launch_bounds__(256) k_agg32(float* __restrict__ ox,
                                               const float* __restrict__ b3) {
    int node = blockIdx.x * 32 + (threadIdx.x >> 3);
    int ch = threadIdx.x & 7;
    if (node >= NN) return;
    const float* h = bufp<HB>();
    float* out = FINAL ? ox : bufp<OB>();

    int beg = g_rowptr[node];
    int end = g_rowptr[node + 1];
    float s = g_nself[node];
    float4 v = __ldg((const float4*)(h + (size_t)node * 32 + ch * 4));
    float ax = v.x * s, ay = v.y * s, az = v.z * s, aw = v.w * s;

    int j = beg;
    if (j + 4 <= end) {
        // prime the pipeline
        float2 e0 = g_csr[j];
        float2 e1 = g_csr[j + 1];
        float2 e2 = g_csr[j + 2];
        float2 e3 = g_csr[j + 3];
        for (; j + 8 <= end; j += 4) {
            // prefetch next quad (independent of current gathers)
            float2 f0 = g_csr[j + 4];
            float2 f1 = g_csr[j + 5];
            float2 f2 = g_csr[j + 6];
            float2 f3 = g_csr[j + 7];
            float4 u0 = __ldg((const float4*)(h + (size_t)__float_as_int(e0.x) * 32 + ch * 4));
            float4 u1 = __ldg((const float4*)(h + (size_t)__float_as_int(e1.x) * 32 + ch * 4));
            float4 u2 = __ldg((const float4*)(h + (size_t)__float_as_int(e2.x) * 32 + ch * 4));
            float4 u3 = __ldg((const float4*)(h + (size_t)__float_as_int(e3.x) * 32 + ch * 4));
            ax += u0.x * e0.y; ay += u0.y * e0.y; az += u0.z * e0.y; aw += u0.w * e0.y;
            ax += u1.x * e1.y; ay += u1.y * e1.y; az += u1.z * e1.y; aw += u1.w * e1.y;
            ax += u2.x * e2.y; ay += u2.y * e2.y; az += u2.z * e2.y; aw += u2.w * e2.y;
            ax += u3.x * e3.y; ay += u3.y * e3.y; az += u3.z * e3.y; aw += u3.w * e3.y;
            e0 = f0; e1 = f1; e2 = f2; e3 = f3;
        }
        // drain last primed quad
        {
            float4 u0 = __ldg((const float4*)(h + (size_t)__float_as_int(e0.x) * 32 + ch * 4));
            float4 u1 = __ldg((const float4*)(h + (size_t)__float_as_int(e1.x) * 32 + ch * 4));
            float4 u2 = __ldg((const float4*)(h + (size_t)__float_as_int(e2.x) * 32 + ch * 4));
            float4 u3 = __ldg((const float4*)(h + (size_t)__float_as_int(e3.x) * 32 + ch * 4));
            ax += u0.x * e0.y; ay += u0.y * e0.y; az += u0.z * e0.y; aw += u0.w * e0.y;
            ax += u1.x * e1.y; ay += u1.y * e1.y; az += u1.z * e1.y; aw += u1.w * e1.y;
            ax += u2.x * e2.y; ay += u2.y * e2.y; az += u2.z * e2.y; aw += u2.w * e2.y;
            ax += u3.x * e3.y; ay += u3.y * e3.y; az += u3.z * e3.y; aw += u3.w * e3.y;
            j += 4;
        }
    }
    for (; j < end; j++) {
        float2 e = g_csr[j];
        float4 u = __ldg((const float4*)(h + (size_t)__float_as_int(e.x) * 32 + ch * 4));
        ax += u.x * e.y; ay += u.y * e.y; az += u.z * e.y; aw += u.w * e.y;
    }

    if (FINAL) {
        float a1v = g_a1[node];
        float a2v = g_a2[node];
        float4 t1 = *(const float4*)(g_bt1 + ch * 4);
        float4 t2 = *(const float4*)(g_bt2 + ch * 4);
        float4 b = *(const float4*)(b3 + ch * 4);
        ax += a2v * t1.x + a1v * t2.x + b.x;
        ay += a2v * t1.y + a1v * t2.y + b.y;
        az += a2v * t1.z + a1v * t2.z + b.z;
        aw += a2v * t1.w + a1v * t2.w + b.w;
        ax = 1.f / (1.f + __expf(-ax));
        ay = 1.f / (1.f + __expf(-ay));
        az = 1.f / (1.f + __expf(-az));
        aw = 1.f / (1.f + __expf(-aw));
    }
    float4 o = {ax, ay, az, aw};
    *(float4*)(out + (size_t)node * 32 + ch * 4) = o;
}

// ---------------- tensor-core GEMM (3xTF32, mma.sync m16n8k8) ----------------
__device__ __forceinline__ void split_tf32(float v, unsigned& hi, unsigned& lo) {
    unsigned h;
    asm("cvt.rna.tf32.f32 %0, %1;" : "=r"(h) : "f"(v));
    float hf = __uint_as_float(h);
    float l = v - hf;
    unsigned lb;
    asm("cvt.rna.tf32.f32 %0, %1;" : "=r"(lb) : "f"(l));
    hi = h; lo = lb;
}

__device__ __forceinline__ void mma_tf32(float* c, const unsigned* a,
                                         unsigned b0, unsigned b1) {
    asm volatile(
        "mma.sync.aligned.m16n8k8.row.col.f32.tf32.tf32.f32 "
        "{%0,%1,%2,%3}, {%4,%5,%6,%7}, {%8,%9}, {%0,%1,%2,%3};\n"
        : "+f"(c[0]), "+f"(c[1]), "+f"(c[2]), "+f"(c[3])
        : "r"(a[0]), "r"(a[1]), "r"(a[2]), "r"(a[3]), "r"(b0), "r"(b1));
}

// C[N,32] = A[N,64] @ Wc[64,32]. 256 thr = 8 warps x m16 = 128 rows/block.
__global__ void __launch_bounds__(256) k_gemm_xc(const float* __restrict__ A) {
    constexpr int IN = 64, OUT = 32;
    constexpr int KT = IN / 8, NT = OUT / 8, S = OUT + 8;
    float* C = g_bufA;

    __shared__ float sHi[IN * S];
    __shared__ float sLo[IN * S];

    int t = threadIdx.x;
    for (int i = t; i < IN * OUT; i += 256) {
        int k = i / OUT, n = i % OUT;
        unsigned hi, lo;
        split_tf32(g_Wc[i], hi, lo);
        sHi[k * S + n] = __uint_as_float(hi);
        sLo[k * S + n] = __uint_as_float(lo);
    }
    __syncthreads();

    int warp = t >> 5, lane = t & 31;
    int g = lane >> 2, tg = lane & 3;
    int row0 = blockIdx.x * 128 + warp * 16;

    float acc[NT][4];
#pragma unroll
    for (int n = 0; n < NT; n++)
#pragma unroll
        for (int j = 0; j < 4; j++) acc[n][j] = 0.f;

    int r0 = row0 + g;       if (r0 >= NN) r0 = NN - 1;
    int r1 = row0 + g + 8;   if (r1 >= NN) r1 = NN - 1;
    const float* Ar0 = A + (size_t)r0 * IN;
    const float* Ar1 = A + (size_t)r1 * IN;

#pragma unroll
    for (int k = 0; k < KT; k++) {
        float a0f = __ldg(Ar0 + k * 8 + tg);
        float a1f = __ldg(Ar1 + k * 8 + tg);
        float a2f = __ldg(Ar0 + k * 8 + tg + 4);
        float a3f = __ldg(Ar1 + k * 8 + tg + 4);
        unsigned ah[4], al[4];
        split_tf32(a0f, ah[0], al[0]);
        split_tf32(a1f, ah[1], al[1]);
        split_tf32(a2f, ah[2], al[2]);
        split_tf32(a3f, ah[3], al[3]);

        int kb0 = (k * 8 + tg) * S;
        int kb1 = (k * 8 + tg + 4) * S;
#pragma unroll
        for (int n = 0; n < NT; n++) {
            int nb = n * 8 + g;
            unsigned bh0 = __float_as_uint(sHi[kb0 + nb]);
            unsigned bh1 = __float_as_uint(sHi[kb1 + nb]);
            unsigned bl0 = __float_as_uint(sLo[kb0 + nb]);
            unsigned bl1 = __float_as_uint(sLo[kb1 + nb]);
            mma_tf32(acc[n], ah, bh0, bh1);
            mma_tf32(acc[n], ah, bl0, bl1);
            mma_tf32(acc[n], al, bh0, bh1);
        }
    }

    int sr0 = row0 + g;
    int sr1 = row0 + g + 8;
#pragma unroll
    for (int n = 0; n < NT; n++) {
        int c0 = n * 8 + tg * 2;
        if (sr0 < NN) {
            float2 o = {acc[n][0], acc[n][1]};
            *(float2*)(C + (size_t)sr0 * OUT + c0) = o;
        }
        if (sr1 < NN) {
            float2 o = {acc[n][2], acc[n][3]};
            *(float2*)(C + (size_t)sr1 * OUT + c0) = o;
        }
    }
}

// ---------------- launch ------------------------------------------------------
extern "C" void kernel_launch(void* const* d_in, const int* in_sizes, int n_in,
                              void* d_out, int out_size) {
    const float* x  = (const float*)d_in[0];
    const int*   ei = (const int*)d_in[1];     // int32 (JAX downcasts int64)
    const float* w  = (const float*)d_in[2];
    const float* W1 = (const float*)d_in[3];
    const float* b1 = (const float*)d_in[4];
    const float* W2 = (const float*)d_in[5];
    const float* b2 = (const float*)d_in[6];
    const float* W3 = (const float*)d_in[7];
    const float* b3 = (const float*)d_in[8];
    float* out = (float*)d_out;

    const int T = 256;
    // --- normalization + CSR build (a1 accumulated inside scatter) ---
    k_init<<<(NN + T - 1) / T, T>>>();
    k_deg<<<(EE + T - 1) / T, T>>>(ei, w);
    k_dinv<<<(NN + T - 1) / T, T>>>();
    k_scan1<<<NB, 1024>>>();
    k_scan2<<<1, 128>>>();
    k_finalize<<<(NN + T - 1) / T, T>>>();
    k_scatter<<<(EE + T - 1) / T, T>>>(ei, w);

    // --- collapsed weights + a2 ---
    k_wc<<<1, 256>>>(W1, W2, W3, b1, b2);
    k_a2<<<(NN + 7) / 8, T>>>();

    // --- xc = x @ Wc  -> bufA ---
    k_gemm_xc<<<(NN + 127) / 128, T>>>(x);

    // --- three width-32 aggregations (8 thr/node, pipelined) ---
    const int GA = (NN + 31) / 32;
    k_agg32<false, BA, BB><<<GA, T>>>(nullptr, nullptr);   // t1 -> bufB
    k_agg32<false, BB, BA><<<GA, T>>>(nullptr, nullptr);   // t2 -> bufA
    k_agg32<true,  BA, BA><<<GA, T>>>(out, b3);            // t3 (+bias,sigmoid) -> out
}